// round 2
// baseline (speedup 1.0000x reference)
#include <cuda_runtime.h>
#include <math.h>
#include <stdint.h>

#define NN   50000
#define NE   400000
#define MEMF 64
#define EFN  32
#define TFN  32
#define HDN  128   // H*D
#define HIDN 512

// ---------------- scratch (static device globals; allowed) ----------------
__device__ float g_Qn[NN * HDN];              // 25.6 MB
__device__ float g_Kmem[NN * HDN];            // 25.6 MB
__device__ float g_kh[(size_t)NE * HDN];      // 204.8 MB
__device__ float g_a[NE * 8];                 // 12.8 MB  (logits -> exp values)
__device__ float g_den[NN * 8];               // 1.6 MB   (0.25/den)
__device__ float g_agg[NN * HDN];             // 25.6 MB
__device__ float g_qconst[HDN];
__device__ int   g_count[NN];
__device__ int   g_off[NN + 1];
__device__ int   g_cursor[NN];
__device__ int   g_eid[NE];

// ---------------- 0: zero counters ----------------
__global__ void zero_count_kernel() {
    int i = blockIdx.x * 256 + threadIdx.x;
    if (i < NN) g_count[i] = 0;
}

// ---------------- 1: qconst = Wq[:,64:96] @ cos(time_b) ----------------
__global__ void qconst_kernel(const float* __restrict__ Wq,
                              const float* __restrict__ time_b) {
    int o = threadIdx.x;  // 128
    float s = 0.f;
    for (int j = 0; j < TFN; j++)
        s += Wq[o * (MEMF + TFN) + MEMF + j] * cosf(time_b[j]);
    g_qconst[o] = s;
}

// ---------------- 2: per-node precompute Qn, Kmem ----------------
// 16 nodes per block, 256 threads; thread o<128 -> Qn row part, o>=128 -> Kmem
__global__ void node_pre_kernel(const float* __restrict__ memory,
                                const float* __restrict__ Wq,
                                const float* __restrict__ Wk) {
    __shared__ __align__(16) float mem_s[16 * 64];
    int nb = blockIdx.x * 16;
    int t = threadIdx.x;
    for (int i = t; i < 16 * 64; i += 256) mem_s[i] = memory[nb * 64 + i];
    __syncthreads();

    float acc[16];
#pragma unroll
    for (int n = 0; n < 16; n++) acc[n] = 0.f;

    const float* wrow = (t < 128) ? (Wq + t * (MEMF + TFN))
                                  : (Wk + (t - 128) * (MEMF + EFN + TFN));
#pragma unroll
    for (int k4 = 0; k4 < 16; k4++) {
        float4 w = *(const float4*)(wrow + k4 * 4);
#pragma unroll
        for (int n = 0; n < 16; n++) {
            float4 x = *(const float4*)(mem_s + n * 64 + k4 * 4);
            acc[n] = fmaf(w.x, x.x, fmaf(w.y, x.y, fmaf(w.z, x.z, fmaf(w.w, x.w, acc[n]))));
        }
    }
    if (t < 128) {
        float qc = g_qconst[t];
#pragma unroll
        for (int n = 0; n < 16; n++) g_Qn[(nb + n) * HDN + t] = acc[n] + qc;
    } else {
        int oo = t - 128;
#pragma unroll
        for (int n = 0; n < 16; n++) g_Kmem[(nb + n) * HDN + oo] = acc[n];
    }
}

// ---------------- 3: CSR build ----------------
__global__ void count_kernel(const int* __restrict__ dst) {
    int e = blockIdx.x * 256 + threadIdx.x;
    if (e < NE) atomicAdd(&g_count[dst[e]], 1);
}

__global__ void scan_kernel() {
    __shared__ int sh[1024];
    int t = threadIdx.x;
    int lo = t * 49; if (lo > NN) lo = NN;
    int hi = lo + 49; if (hi > NN) hi = NN;
    int s = 0;
    for (int i = lo; i < hi; i++) s += g_count[i];
    sh[t] = s;
    __syncthreads();
    for (int off = 1; off < 1024; off <<= 1) {
        int v = (t >= off) ? sh[t - off] : 0;
        __syncthreads();
        sh[t] += v;
        __syncthreads();
    }
    int base = (t == 0) ? 0 : sh[t - 1];
    for (int i = lo; i < hi; i++) {
        g_off[i] = base;
        g_cursor[i] = base;
        base += g_count[i];
    }
    if (t == 1023) g_off[NN] = NE;
}

__global__ void scatter_kernel(const int* __restrict__ dst) {
    int e = blockIdx.x * 256 + threadIdx.x;
    if (e < NE) {
        int p = atomicAdd(&g_cursor[dst[e]], 1);
        g_eid[p] = e;
    }
}

// ---------------- 4: per-edge kh + attention logits ----------------
// 8 warps / block, each warp handles 8 edges => 64 edges per block.
// Wt[j][o] in shared (row-padded to 132 floats): rows 0..31 = Wk edge-feat
// cols, rows 32..63 = Wk time cols. Coalesced global read, transposed store.
#define WT_PITCH 132
__global__ void edge_kernel(const int* __restrict__ src, const int* __restrict__ dst,
                            const float* __restrict__ ts, const float* __restrict__ efeats,
                            const float* __restrict__ ets, const float* __restrict__ Wk,
                            const float* __restrict__ time_w, const float* __restrict__ time_b) {
    __shared__ __align__(16) float Wt[64 * WT_PITCH];
    int t = threadIdx.x;
    // coalesced read of Wk[o][64+j] (64 consecutive floats per row)
    for (int i = t; i < 128 * 64; i += 256) {
        int o = i >> 6, j = i & 63;
        Wt[j * WT_PITCH + o] = Wk[o * 128 + 64 + j];
    }
    int warp = t >> 5, lane = t & 31;
    float tw = time_w[lane], tb = time_b[lane];
    __syncthreads();

    int ebase = blockIdx.x * 64 + warp * 8;  // NE divisible by 64
#pragma unroll 1
    for (int ei = 0; ei < 8; ei++) {
        int e = ebase + ei;
        int s = src[e], d = dst[e];
        float ef = efeats[e * EFN + lane];
        float td = ets[e] - ts[s];
        float kt = cosf(td * tw + tb);

        float4 acc = make_float4(0.f, 0.f, 0.f, 0.f);
#pragma unroll
        for (int j = 0; j < 32; j++) {
            float efj = __shfl_sync(0xffffffffu, ef, j);
            float ktj = __shfl_sync(0xffffffffu, kt, j);
            float4 wb = *(const float4*)(Wt + j * WT_PITCH + lane * 4);
            float4 wc = *(const float4*)(Wt + (32 + j) * WT_PITCH + lane * 4);
            acc.x = fmaf(efj, wb.x, fmaf(ktj, wc.x, acc.x));
            acc.y = fmaf(efj, wb.y, fmaf(ktj, wc.y, acc.y));
            acc.z = fmaf(efj, wb.z, fmaf(ktj, wc.z, acc.z));
            acc.w = fmaf(efj, wb.w, fmaf(ktj, wc.w, acc.w));
        }
        float4 km = *(const float4*)(g_Kmem + (size_t)s * HDN + lane * 4);
        float4 kh = make_float4(km.x + acc.x, km.y + acc.y, km.z + acc.z, km.w + acc.w);
        *(float4*)(g_kh + (size_t)e * HDN + lane * 4) = kh;

        float4 qn = *(const float4*)(g_Qn + (size_t)d * HDN + lane * 4);
        float p = qn.x * kh.x + qn.y * kh.y + qn.z * kh.z + qn.w * kh.w;
        // head = 16 consecutive outputs = 4 consecutive lanes
        p += __shfl_xor_sync(0xffffffffu, p, 1);
        p += __shfl_xor_sync(0xffffffffu, p, 2);
        if ((lane & 3) == 0) g_a[e * 8 + (lane >> 2)] = p;
    }
}

// ---------------- 5: per-(node,head) softmax (max, exp, 1/den) ----------------
__global__ void softmax_kernel() {
    int idx = blockIdx.x * 256 + threadIdx.x;
    if (idx >= NN * 8) return;
    int n = idx >> 3, h = idx & 7;
    int b = g_off[n], e1 = g_off[n + 1];
    float m = -3.4e38f;
    for (int i = b; i < e1; i++) {
        float v = g_a[g_eid[i] * 8 + h];
        m = fmaxf(m, v);
    }
    float den = 0.f;
    for (int i = b; i < e1; i++) {
        int ee = g_eid[i];
        float v = expf(g_a[ee * 8 + h] - m);
        g_a[ee * 8 + h] = v;
        den += v;
    }
    g_den[idx] = 0.25f / den;  // fold 1/sqrt(D)=0.25
}

// ---------------- 6: gather aggregation ----------------
// 2 nodes per 256-thread block; 128 threads (= one o each) per node
__global__ void gather_kernel() {
    int n = blockIdx.x * 2 + (threadIdx.x >> 7);
    int o = threadIdx.x & 127;
    int h = o >> 4;
    int b = g_off[n], e1 = g_off[n + 1];
    float scale = g_den[n * 8 + h];
    float s = 0.f;
    for (int i = b; i < e1; i++) {
        int e = g_eid[i];
        s = fmaf(g_a[e * 8 + h], g_kh[(size_t)e * HDN + o], s);
    }
    g_agg[n * HDN + o] = s * scale;
}

// ---------------- 7: merge MLP: relu([agg||mem] @ W1^T + b1) @ W2^T + b2 ----
// 16 nodes / block, 128 threads. W1 staged via shared in coalesced tiles.
__global__ void merge_kernel(const float* __restrict__ memory,
                             const float* __restrict__ W1, const float* __restrict__ b1,
                             const float* __restrict__ W2, const float* __restrict__ b2,
                             float* __restrict__ out) {
    __shared__ float Xs[16][193];
    __shared__ float W1s[128][49];
    __shared__ float Hs[16][132];
    int nb = blockIdx.x * 16;
    int t = threadIdx.x;  // 128

    for (int i = t; i < 16 * 192; i += 128) {
        int n = i / 192, c = i - n * 192;
        Xs[n][c] = (c < HDN) ? g_agg[(nb + n) * HDN + c]
                             : memory[(nb + n) * MEMF + (c - HDN)];
    }
    int n0 = t >> 4, oc0 = t & 15;
    int n1 = (128 + t) >> 4, oc1 = t & 15;
    float oacc0 = b2[oc0], oacc1 = b2[oc1];
    __syncthreads();

    for (int hct = 0; hct < 4; hct++) {
        int hc = hct * 128 + t;
        float acc[16];
#pragma unroll
        for (int n = 0; n < 16; n++) acc[n] = 0.f;

        for (int ktile = 0; ktile < 4; ktile++) {
            __syncthreads();  // previous W1s reads / previous-tile Hs reads done
            for (int i = t; i < 128 * 48; i += 128) {
                int r = i / 48, c = i - r * 48;
                W1s[r][c] = W1[(hct * 128 + r) * 192 + ktile * 48 + c];
            }
            __syncthreads();
#pragma unroll 4
            for (int k = 0; k < 48; k++) {
                float w = W1s[t][k];
                int kg = ktile * 48 + k;
#pragma unroll
                for (int n = 0; n < 16; n++) acc[n] = fmaf(w, Xs[n][kg], acc[n]);
            }
        }
        float bb = b1[hc];
        __syncthreads();
#pragma unroll
        for (int n = 0; n < 16; n++) Hs[n][t] = fmaxf(acc[n] + bb, 0.f);
        __syncthreads();

        const float* w2a = W2 + oc0 * HIDN + hct * 128;
        const float* w2b = W2 + oc1 * HIDN + hct * 128;
        float s0 = 0.f, s1 = 0.f;
#pragma unroll 4
        for (int j = 0; j < 128; j++) {
            s0 = fmaf(Hs[n0][j], w2a[j], s0);
            s1 = fmaf(Hs[n1][j], w2b[j], s1);
        }
        oacc0 += s0;
        oacc1 += s1;
    }
    out[(nb + n0) * 16 + oc0] = oacc0;
    out[(nb + n1) * 16 + oc1] = oacc1;
}

// ---------------- launch ----------------
extern "C" void kernel_launch(void* const* d_in, const int* in_sizes, int n_in,
                              void* d_out, int out_size) {
    const int*   src    = (const int*)d_in[0];
    const int*   dst    = (const int*)d_in[1];
    const float* memory = (const float*)d_in[2];
    const float* ts     = (const float*)d_in[3];
    const float* efeats = (const float*)d_in[4];
    const float* ets    = (const float*)d_in[5];
    const float* Wq     = (const float*)d_in[6];
    const float* Wk     = (const float*)d_in[7];
    const float* W1     = (const float*)d_in[8];
    const float* b1     = (const float*)d_in[9];
    const float* W2     = (const float*)d_in[10];
    const float* b2     = (const float*)d_in[11];
    const float* time_w = (const float*)d_in[12];
    const float* time_b = (const float*)d_in[13];
    float* out = (float*)d_out;

    zero_count_kernel<<<(NN + 255) / 256, 256>>>();
    qconst_kernel<<<1, 128>>>(Wq, time_b);
    node_pre_kernel<<<NN / 16, 256>>>(memory, Wq, Wk);
    count_kernel<<<(NE + 255) / 256, 256>>>(dst);
    scan_kernel<<<1, 1024>>>();
    scatter_kernel<<<(NE + 255) / 256, 256>>>(dst);
    edge_kernel<<<NE / 64, 256>>>(src, dst, ts, efeats, ets, Wk, time_w, time_b);
    softmax_kernel<<<(NN * 8 + 255) / 256, 256>>>();
    gather_kernel<<<NN / 2, 256>>>();
    merge_kernel<<<NN / 16, 128>>>(memory, W1, b1, W2, b2, out);
}

// round 3
// speedup vs baseline: 1.8944x; 1.8944x over previous
#include <cuda_runtime.h>
#include <math.h>
#include <stdint.h>

#define NN   50000
#define NE   400000
#define MEMF 64
#define EFN  32
#define TFN  32
#define HDN  128   // H*D
#define HIDN 512

typedef unsigned long long ull;

__device__ __forceinline__ ull ffma2(ull a, ull b, ull c) {
    ull d;
    asm("fma.rn.f32x2 %0, %1, %2, %3;" : "=l"(d) : "l"(a), "l"(b), "l"(c));
    return d;
}
__device__ __forceinline__ ull dup2(float x) {
    ull d;
    asm("mov.b64 %0, {%1, %1};" : "=l"(d) : "f"(x));
    return d;
}
__device__ __forceinline__ float2 u2f(ull v) {
    float2 r;
    asm("mov.b64 {%0, %1}, %2;" : "=f"(r.x), "=f"(r.y) : "l"(v));
    return r;
}

// ---------------- scratch ----------------
__device__ float g_Qn[NN * HDN];
__device__ float g_Kmem[NN * HDN];
__device__ float g_kh[(size_t)NE * HDN];      // 204.8 MB
__device__ float g_a[NE * 8];
__device__ float g_den[NN * 8];
__device__ float g_agg[NN * HDN];
__device__ float g_hid[(size_t)NN * HIDN];    // 102.4 MB
__device__ float g_qconst[HDN];
__device__ int   g_count[NN];
__device__ int   g_off[NN + 1];
__device__ int   g_cursor[NN];
__device__ int   g_eid[NE];

// ---------------- 0: zero counters ----------------
__global__ void zero_count_kernel() {
    int i = blockIdx.x * 256 + threadIdx.x;
    if (i < NN) g_count[i] = 0;
}

// ---------------- 1: qconst = Wq[:,64:96] @ cos(time_b) ----------------
__global__ void qconst_kernel(const float* __restrict__ Wq,
                              const float* __restrict__ time_b) {
    int o = threadIdx.x;  // 128
    float s = 0.f;
    for (int j = 0; j < TFN; j++)
        s += Wq[o * (MEMF + TFN) + MEMF + j] * cosf(time_b[j]);
    g_qconst[o] = s;
}

// ---------------- 2: per-node precompute Qn, Kmem ----------------
__global__ void node_pre_kernel(const float* __restrict__ memory,
                                const float* __restrict__ Wq,
                                const float* __restrict__ Wk) {
    __shared__ __align__(16) float mem_s[16 * 64];
    int nb = blockIdx.x * 16;
    int t = threadIdx.x;
    for (int i = t; i < 16 * 64; i += 256) mem_s[i] = memory[nb * 64 + i];
    __syncthreads();

    float acc[16];
#pragma unroll
    for (int n = 0; n < 16; n++) acc[n] = 0.f;

    const float* wrow = (t < 128) ? (Wq + t * (MEMF + TFN))
                                  : (Wk + (t - 128) * (MEMF + EFN + TFN));
#pragma unroll
    for (int k4 = 0; k4 < 16; k4++) {
        float4 w = *(const float4*)(wrow + k4 * 4);
#pragma unroll
        for (int n = 0; n < 16; n++) {
            float4 x = *(const float4*)(mem_s + n * 64 + k4 * 4);
            acc[n] = fmaf(w.x, x.x, fmaf(w.y, x.y, fmaf(w.z, x.z, fmaf(w.w, x.w, acc[n]))));
        }
    }
    if (t < 128) {
        float qc = g_qconst[t];
#pragma unroll
        for (int n = 0; n < 16; n++) g_Qn[(nb + n) * HDN + t] = acc[n] + qc;
    } else {
        int oo = t - 128;
#pragma unroll
        for (int n = 0; n < 16; n++) g_Kmem[(nb + n) * HDN + oo] = acc[n];
    }
}

// ---------------- 3: CSR build ----------------
__global__ void count_kernel(const int* __restrict__ dst) {
    int e = blockIdx.x * 256 + threadIdx.x;
    if (e < NE) atomicAdd(&g_count[dst[e]], 1);
}

__global__ void scan_kernel() {
    __shared__ int sh[1024];
    int t = threadIdx.x;
    int lo = t * 49; if (lo > NN) lo = NN;
    int hi = lo + 49; if (hi > NN) hi = NN;
    int s = 0;
    for (int i = lo; i < hi; i++) s += g_count[i];
    sh[t] = s;
    __syncthreads();
    for (int off = 1; off < 1024; off <<= 1) {
        int v = (t >= off) ? sh[t - off] : 0;
        __syncthreads();
        sh[t] += v;
        __syncthreads();
    }
    int base = (t == 0) ? 0 : sh[t - 1];
    for (int i = lo; i < hi; i++) {
        g_off[i] = base;
        g_cursor[i] = base;
        base += g_count[i];
    }
    if (t == 1023) g_off[NN] = NE;
}

__global__ void scatter_kernel(const int* __restrict__ dst) {
    int e = blockIdx.x * 256 + threadIdx.x;
    if (e < NE) {
        int p = atomicAdd(&g_cursor[dst[e]], 1);
        g_eid[p] = e;
    }
}

// ---------------- 4: edge GEMM: kh + attention logits ----------------
// 128 edges/block, 256 threads. Register tile 4 edges x 16 outputs (f32x2 pairs).
// Output columns per thread: o = oh*4 + 32*c (c=0..3)  [conflict-free LDS]
// Two K-passes: p=0 edge feats (Wk cols 64..95), p=1 time feats (96..127).
#define EPB 128
__global__ __launch_bounds__(256) void edge_kernel(
    const int* __restrict__ src, const int* __restrict__ dst,
    const float* __restrict__ ts, const float* __restrict__ efeats,
    const float* __restrict__ ets, const float* __restrict__ Wk,
    const float* __restrict__ time_w, const float* __restrict__ time_b) {
    __shared__ __align__(16) float As[32 * 132];
    __shared__ __align__(16) float Wt[32 * 132];
    __shared__ float s_td[EPB];
    __shared__ int   s_src[EPB], s_dst[EPB];
    __shared__ float s_tw[32], s_tb[32];
    int t = threadIdx.x;
    int e0 = blockIdx.x * EPB;
    if (t < EPB) {
        int e = e0 + t;
        int sv = src[e];
        s_src[t] = sv;
        s_dst[t] = dst[e];
        s_td[t] = ets[e] - ts[sv];
    }
    if (t < 32) { s_tw[t] = time_w[t]; s_tb[t] = time_b[t]; }
    int oh = t & 7, ne = t >> 3;
    ull acc[4][8] = {};
    __syncthreads();

    for (int p = 0; p < 2; p++) {
        if (p) __syncthreads();
        for (int i = t; i < 128 * 32; i += 256) {
            int o = i >> 5, kk = i & 31;
            Wt[kk * 132 + o] = Wk[o * 128 + 64 + p * 32 + kk];
        }
        if (p == 0) {
            for (int i = t; i < EPB * 32; i += 256) {
                int e = i >> 5, kk = i & 31;
                As[kk * 132 + e] = efeats[(e0 + e) * 32 + kk];
            }
        } else {
            for (int i = t; i < EPB * 32; i += 256) {
                int e = i >> 5, kk = i & 31;
                As[kk * 132 + e] = cosf(s_td[e] * s_tw[kk] + s_tb[kk]);
            }
        }
        __syncthreads();
#pragma unroll
        for (int kk = 0; kk < 32; kk++) {
            float4 av = *(const float4*)&As[kk * 132 + ne * 4];
            ull ad[4] = {dup2(av.x), dup2(av.y), dup2(av.z), dup2(av.w)};
#pragma unroll
            for (int c = 0; c < 4; c++) {
                ulonglong2 w = *(const ulonglong2*)&Wt[kk * 132 + oh * 4 + c * 32];
#pragma unroll
                for (int ei = 0; ei < 4; ei++) {
                    acc[ei][2 * c]     = ffma2(ad[ei], w.x, acc[ei][2 * c]);
                    acc[ei][2 * c + 1] = ffma2(ad[ei], w.y, acc[ei][2 * c + 1]);
                }
            }
        }
    }
    // epilogue: add Kmem[src], store kh, logits via Qn[dst]
#pragma unroll
    for (int ei = 0; ei < 4; ei++) {
        int el = ne * 4 + ei, e = e0 + el;
        int sv = s_src[el], dv = s_dst[el];
#pragma unroll
        for (int c = 0; c < 4; c++) {
            int o = oh * 4 + c * 32;
            float4 km = *(const float4*)&g_Kmem[sv * HDN + o];
            float2 lo = u2f(acc[ei][2 * c]), hi = u2f(acc[ei][2 * c + 1]);
            float4 kh = make_float4(lo.x + km.x, lo.y + km.y, hi.x + km.z, hi.y + km.w);
            *(float4*)&g_kh[(size_t)e * HDN + o] = kh;
            float4 qn = *(const float4*)&g_Qn[dv * HDN + o];
            float pc = qn.x * kh.x + qn.y * kh.y + qn.z * kh.z + qn.w * kh.w;
            pc += __shfl_xor_sync(0xffffffffu, pc, 1);
            pc += __shfl_xor_sync(0xffffffffu, pc, 2);
            if ((oh & 3) == 0) g_a[e * 8 + (oh >> 2) + 2 * c] = pc;
        }
    }
}

// ---------------- 5: per-(node,head) softmax ----------------
__global__ void softmax_kernel() {
    int idx = blockIdx.x * 256 + threadIdx.x;
    if (idx >= NN * 8) return;
    int n = idx >> 3, h = idx & 7;
    int b = g_off[n], e1 = g_off[n + 1];
    float m = -3.4e38f;
    for (int i = b; i < e1; i++) {
        float v = g_a[g_eid[i] * 8 + h];
        m = fmaxf(m, v);
    }
    float den = 0.f;
    for (int i = b; i < e1; i++) {
        int ee = g_eid[i];
        float v = expf(g_a[ee * 8 + h] - m);
        g_a[ee * 8 + h] = v;
        den += v;
    }
    g_den[idx] = 0.25f / den;
}

// ---------------- 6: gather aggregation ----------------
__global__ void gather_kernel() {
    int n = blockIdx.x * 2 + (threadIdx.x >> 7);
    int o = threadIdx.x & 127;
    int h = o >> 4;
    int b = g_off[n], e1 = g_off[n + 1];
    float scale = g_den[n * 8 + h];
    float s = 0.f;
    for (int i = b; i < e1; i++) {
        int e = g_eid[i];
        s = fmaf(g_a[e * 8 + h], g_kh[(size_t)e * HDN + o], s);
    }
    g_agg[n * HDN + o] = s * scale;
}

// ---------------- 7a: hidden GEMM: g_hid = relu([agg||mem] @ W1^T + b1) ------
// Block tile: 64 nodes x 256 hidden. grid (782, 2). 256 threads.
// Thread tile: 4 nodes x 16 hidden (as 8 f32x2 pairs, h = oh*4 + 64*c).
__global__ __launch_bounds__(256) void hid_kernel(
    const float* __restrict__ memory, const float* __restrict__ W1,
    const float* __restrict__ b1) {
    __shared__ __align__(16) float Xs[32 * 68];
    __shared__ __align__(16) float W1s[32 * 260];
    __shared__ __align__(16) float b1s[256];
    int t = threadIdx.x;
    int nb = blockIdx.x * 64;
    int y = blockIdx.y;            // 0..1 -> hidden chunk of 256
    int oh = t & 15, ne = t >> 4;
    b1s[t] = b1[y * 256 + t];
    ull acc[4][8] = {};

    for (int kt = 0; kt < 6; kt++) {
        __syncthreads();
        for (int i = t; i < 64 * 32; i += 256) {
            int n = i >> 5, kk = i & 31;
            int row = nb + n; if (row >= NN) row = NN - 1;
            int kg = kt * 32 + kk;
            Xs[kk * 68 + n] = (kg < HDN) ? g_agg[row * HDN + kg]
                                         : memory[row * MEMF + kg - HDN];
        }
        for (int i = t; i < 256 * 32; i += 256) {
            int h = i >> 5, kk = i & 31;
            W1s[kk * 260 + h] = W1[(y * 256 + h) * 192 + kt * 32 + kk];
        }
        __syncthreads();
#pragma unroll
        for (int kk = 0; kk < 32; kk++) {
            float4 av = *(const float4*)&Xs[kk * 68 + ne * 4];
            ull ad[4] = {dup2(av.x), dup2(av.y), dup2(av.z), dup2(av.w)};
#pragma unroll
            for (int c = 0; c < 4; c++) {
                ulonglong2 w = *(const ulonglong2*)&W1s[kk * 260 + oh * 4 + c * 64];
#pragma unroll
                for (int ni = 0; ni < 4; ni++) {
                    acc[ni][2 * c]     = ffma2(ad[ni], w.x, acc[ni][2 * c]);
                    acc[ni][2 * c + 1] = ffma2(ad[ni], w.y, acc[ni][2 * c + 1]);
                }
            }
        }
    }
#pragma unroll
    for (int ni = 0; ni < 4; ni++) {
        int n = nb + ne * 4 + ni;
        if (n < NN) {
#pragma unroll
            for (int c = 0; c < 4; c++) {
                int hl = oh * 4 + c * 64;
                float4 bb = *(const float4*)&b1s[hl];
                float2 lo = u2f(acc[ni][2 * c]), hi = u2f(acc[ni][2 * c + 1]);
                float4 v = make_float4(fmaxf(lo.x + bb.x, 0.f), fmaxf(lo.y + bb.y, 0.f),
                                       fmaxf(hi.x + bb.z, 0.f), fmaxf(hi.y + bb.w, 0.f));
                *(float4*)&g_hid[(size_t)n * HIDN + y * 256 + hl] = v;
            }
        }
    }
}

// ---------------- 7b: out = g_hid @ W2^T + b2 ----------------
// 16 nodes/block, 256 threads (one thread per (node, out)); W2 staged padded.
__global__ __launch_bounds__(256) void out_kernel(
    const float* __restrict__ W2, const float* __restrict__ b2,
    float* __restrict__ out) {
    __shared__ __align__(16) float W2s[16 * 516];
    int t = threadIdx.x;
    int nb = blockIdx.x * 16;
    for (int i = t; i < 16 * 512; i += 256) {
        int o = i >> 9, j = i & 511;
        W2s[o * 516 + j] = W2[i];
    }
    __syncthreads();
    int o = t & 15, n = nb + (t >> 4);
    float acc = b2[o];
    const float* hrow = g_hid + (size_t)n * HIDN;
    const float* wrow = W2s + o * 516;
#pragma unroll 8
    for (int j4 = 0; j4 < 128; j4++) {
        float4 h = *(const float4*)&hrow[j4 * 4];
        float4 w = *(const float4*)&wrow[j4 * 4];
        acc = fmaf(h.x, w.x, fmaf(h.y, w.y, fmaf(h.z, w.z, fmaf(h.w, w.w, acc))));
    }
    out[n * 16 + o] = acc;
}

// ---------------- launch ----------------
extern "C" void kernel_launch(void* const* d_in, const int* in_sizes, int n_in,
                              void* d_out, int out_size) {
    const int*   src    = (const int*)d_in[0];
    const int*   dst    = (const int*)d_in[1];
    const float* memory = (const float*)d_in[2];
    const float* ts     = (const float*)d_in[3];
    const float* efeats = (const float*)d_in[4];
    const float* ets    = (const float*)d_in[5];
    const float* Wq     = (const float*)d_in[6];
    const float* Wk     = (const float*)d_in[7];
    const float* W1     = (const float*)d_in[8];
    const float* b1     = (const float*)d_in[9];
    const float* W2     = (const float*)d_in[10];
    const float* b2     = (const float*)d_in[11];
    const float* time_w = (const float*)d_in[12];
    const float* time_b = (const float*)d_in[13];
    float* out = (float*)d_out;

    zero_count_kernel<<<(NN + 255) / 256, 256>>>();
    qconst_kernel<<<1, 128>>>(Wq, time_b);
    node_pre_kernel<<<NN / 16, 256>>>(memory, Wq, Wk);
    count_kernel<<<(NE + 255) / 256, 256>>>(dst);
    scan_kernel<<<1, 1024>>>();
    scatter_kernel<<<(NE + 255) / 256, 256>>>(dst);
    edge_kernel<<<NE / EPB, 256>>>(src, dst, ts, efeats, ets, Wk, time_w, time_b);
    softmax_kernel<<<(NN * 8 + 255) / 256, 256>>>();
    gather_kernel<<<NN / 2, 256>>>();
    hid_kernel<<<dim3((NN + 63) / 64, 2), 256>>>(memory, W1, b1);
    out_kernel<<<NN / 16, 256>>>(W2, b2, out);
}